// round 11
// baseline (speedup 1.0000x reference)
#include <cuda_runtime.h>
#include <math.h>

#define B 192
#define D 2048
#define H 128
#define LOG2PI 1.8378770664093453f
#define IG 4   // i-rows per main-kernel block

// Scratch (device globals — no allocation allowed)
__device__ __align__(16) float g_h1[B * 2 * H];
__device__ __align__(16) float g_h2[B * 2 * H];
__device__ __align__(16) float g_mu[B * D];
__device__ __align__(16) float g_scale[B * D];
__device__ float g_lvpart[B * 8];

// ---------------------------------------------------------------------------
// Kernel 1 (R4-exact, measured best): h1 = relu(q @ w1^T + b1), both heads.
// 8x4 register-tiled warps, lanes split K=2048. 192 blocks.
// ---------------------------------------------------------------------------
__global__ void __launch_bounds__(256) gemm1_kernel(
    const float* __restrict__ q,
    const float* __restrict__ mw, const float* __restrict__ mb,
    const float* __restrict__ lw, const float* __restrict__ lb)
{
    int warp = threadIdx.x >> 5;
    int lane = threadIdx.x & 31;
    int cg   = blockIdx.x * 8 + warp;   // colgroup 0..63
    int row0 = blockIdx.y * 8;
    int col0 = cg * 4;

    const float* wbase;
    const float* bbase;
    int clocal;
    if (col0 < H) { wbase = mw; bbase = mb; clocal = col0;     }
    else          { wbase = lw; bbase = lb; clocal = col0 - H; }

    const float4* q4 = (const float4*)q;
    const float4* w4 = (const float4*)wbase;

    float acc[8][4];
    #pragma unroll
    for (int r = 0; r < 8; ++r)
        #pragma unroll
        for (int c = 0; c < 4; ++c) acc[r][c] = 0.f;

    #pragma unroll 4
    for (int it = 0; it < (D / 4) / 32; ++it) {   // 16 iters
        int k4 = lane + it * 32;
        float4 b[4];
        #pragma unroll
        for (int c = 0; c < 4; ++c) b[c] = w4[(size_t)(clocal + c) * (D / 4) + k4];
        #pragma unroll
        for (int r = 0; r < 8; ++r) {
            float4 a = q4[(size_t)(row0 + r) * (D / 4) + k4];
            #pragma unroll
            for (int c = 0; c < 4; ++c)
                acc[r][c] += a.x * b[c].x + a.y * b[c].y
                           + a.z * b[c].z + a.w * b[c].w;
        }
    }

    float bv[4];
    #pragma unroll
    for (int c = 0; c < 4; ++c) bv[c] = bbase[clocal + c];

    #pragma unroll
    for (int r = 0; r < 8; ++r)
        #pragma unroll
        for (int c = 0; c < 4; ++c) {
            float v = acc[r][c];
            #pragma unroll
            for (int o = 16; o; o >>= 1) v += __shfl_xor_sync(0xffffffffu, v, o);
            if (lane == 0)
                g_h1[(row0 + r) * 256 + col0 + c] = fmaxf(v + bv[c], 0.f);
        }
}

// ---------------------------------------------------------------------------
// Kernel 2 (R4-exact): h2 = relu(h1 @ w2^T + b2). 8 rows per block.
// ---------------------------------------------------------------------------
__global__ void __launch_bounds__(256) gemm2_kernel(
    const float* __restrict__ mw, const float* __restrict__ mb,
    const float* __restrict__ lw, const float* __restrict__ lb)
{
    __shared__ float s[8][256];
    int row0 = blockIdx.x * 8;
    int tid = threadIdx.x;

    #pragma unroll
    for (int r = 0; r < 8; ++r)
        s[r][tid] = g_h1[(row0 + r) * 256 + tid];
    __syncthreads();

    const float* w;
    float bias;
    int hoff;
    if (tid < H) { w = mw + (size_t)tid * H;       bias = mb[tid];     hoff = 0; }
    else         { w = lw + (size_t)(tid - H) * H; bias = lb[tid - H]; hoff = H; }

    float acc[8];
    #pragma unroll
    for (int r = 0; r < 8; ++r) acc[r] = bias;

    #pragma unroll 8
    for (int k = 0; k < H; ++k) {
        float wv = w[k];
        #pragma unroll
        for (int r = 0; r < 8; ++r) acc[r] += s[r][hoff + k] * wv;
    }
    #pragma unroll
    for (int r = 0; r < 8; ++r)
        g_h2[(row0 + r) * 256 + tid] = fmaxf(acc[r], 0.f);
}

// ---------------------------------------------------------------------------
// Kernel 3 (R4-exact): layer-3 for both heads, 8 rows per block.
// ---------------------------------------------------------------------------
__global__ void __launch_bounds__(256) gemm3_kernel(
    const float* __restrict__ mw, const float* __restrict__ mb,
    const float* __restrict__ lw, const float* __restrict__ lb)
{
    __shared__ float4 s4[8][32];
    __shared__ float red[8][8];

    int tid  = threadIdx.x;
    int row0 = blockIdx.y * 8;
    int head = blockIdx.x >> 3;        // 0 = mu, 1 = lv

    {
        int r  = tid >> 5;
        int kk = tid & 31;
        s4[r][kk] = ((const float4*)(g_h2 + (row0 + r) * 256 + head * H))[kk];
    }
    __syncthreads();

    int d = (blockIdx.x & 7) * 256 + tid;
    const float* wrow = (head ? lw : mw) + (size_t)d * H;
    const float* bptr = head ? lb : mb;

    float acc[8];
    #pragma unroll
    for (int r = 0; r < 8; ++r) acc[r] = 0.f;

    #pragma unroll
    for (int kk = 0; kk < 32; ++kk) {
        float4 w = ((const float4*)wrow)[kk];
        #pragma unroll
        for (int r = 0; r < 8; ++r) {
            float4 h = s4[r][kk];
            acc[r] += w.x * h.x + w.y * h.y + w.z * h.z + w.w * h.w;
        }
    }
    float bias = bptr[d];

    if (!head) {
        #pragma unroll
        for (int r = 0; r < 8; ++r)
            g_mu[(size_t)(row0 + r) * D + d] = fmaxf(acc[r] + bias, 0.f);
    } else {
        int lane = tid & 31, wid = tid >> 5;
        #pragma unroll
        for (int r = 0; r < 8; ++r) {
            float v = fmaxf(acc[r] + bias, 0.f);
            g_scale[(size_t)(row0 + r) * D + d] = expf(0.25f * v);
            #pragma unroll
            for (int o = 16; o; o >>= 1) v += __shfl_xor_sync(0xffffffffu, v, o);
            if (lane == 0) red[wid][r] = v;
        }
        __syncthreads();
        if (tid == 0) {
            #pragma unroll
            for (int r = 0; r < 8; ++r) {
                float sum = 0.f;
                #pragma unroll
                for (int k = 0; k < 8; ++k) sum += red[k][r];
                g_lvpart[(row0 + r) * 8 + (blockIdx.x & 7)] = sum;
            }
        }
    }
}

// ---------------------------------------------------------------------------
// Kernel 4 (HBM-bound mainloop): block per (j, 4 i-rows), 256 threads,
// mu/scale in registers. CHANGE vs R10: ALL FOUR rows' eps loads (8 float4)
// issued back-to-back before any consumption -> per-thread MLP 4 -> 8.
// R10 evidence: MLP 2->4 moved DRAM 80.6%->82.8% even with occupancy drop;
// in-flight/SM = MLP x warps is the controlling product (8x24=192 > 4x32=128).
// ---------------------------------------------------------------------------
__global__ void __launch_bounds__(256) main_kernel(
    const float* __restrict__ eps,
    float* __restrict__ p,
    float* __restrict__ lp)
{
    __shared__ float red[8][IG];
    __shared__ float s_t;

    int j   = blockIdx.x % B;
    int ig  = blockIdx.x / B;
    int tid = threadIdx.x;

    const float4* m4 = (const float4*)g_mu    + (size_t)j * (D / 4);
    const float4* s4 = (const float4*)g_scale + (size_t)j * (D / 4);
    float4 m0 = m4[tid], m1 = m4[tid + 256];
    float4 s0 = s4[tid], s1 = s4[tid + 256];

    if (tid == 0) {
        float sum = 0.f;
        #pragma unroll
        for (int k = 0; k < 8; ++k) sum += g_lvpart[j * 8 + k];
        s_t = -0.25f * sum - 0.5f * (float)D * LOG2PI;
    }

    // row base offsets (in float4 units)
    size_t rbase[IG];
    #pragma unroll
    for (int r = 0; r < IG; ++r)
        rbase[r] = ((size_t)(ig * IG + r) * B + j) * (D / 4);

    // issue all 8 eps loads before any consumption
    float4 e[IG][2];
    #pragma unroll
    for (int r = 0; r < IG; ++r) {
        const float4* e4 = (const float4*)eps + rbase[r];
        e[r][0] = __ldcs(&e4[tid]);
        e[r][1] = __ldcs(&e4[tid + 256]);
    }

    float acc[IG];
    #pragma unroll
    for (int r = 0; r < IG; ++r) {
        float4* p4 = (float4*)p + rbase[r];
        float4 o;
        o.x = fmaf(e[r][0].x, s0.x, m0.x);
        o.y = fmaf(e[r][0].y, s0.y, m0.y);
        o.z = fmaf(e[r][0].z, s0.z, m0.z);
        o.w = fmaf(e[r][0].w, s0.w, m0.w);
        __stcs(&p4[tid], o);
        o.x = fmaf(e[r][1].x, s1.x, m1.x);
        o.y = fmaf(e[r][1].y, s1.y, m1.y);
        o.z = fmaf(e[r][1].z, s1.z, m1.z);
        o.w = fmaf(e[r][1].w, s1.w, m1.w);
        __stcs(&p4[tid + 256], o);
        acc[r] = e[r][0].x * e[r][0].x + e[r][0].y * e[r][0].y
               + e[r][0].z * e[r][0].z + e[r][0].w * e[r][0].w
               + e[r][1].x * e[r][1].x + e[r][1].y * e[r][1].y
               + e[r][1].z * e[r][1].z + e[r][1].w * e[r][1].w;
    }

    int lane = tid & 31, wid = tid >> 5;
    #pragma unroll
    for (int r = 0; r < IG; ++r) {
        float v = acc[r];
        #pragma unroll
        for (int o = 16; o; o >>= 1) v += __shfl_xor_sync(0xffffffffu, v, o);
        if (lane == 0) red[wid][r] = v;
    }
    __syncthreads();
    if (tid < IG) {
        float v = 0.f;
        #pragma unroll
        for (int k = 0; k < 8; ++k) v += red[k][tid];
        lp[(size_t)(ig * IG + tid) * B + j] = -0.5f * v + s_t;
    }
}

// ---------------------------------------------------------------------------
extern "C" void kernel_launch(void* const* d_in, const int* in_sizes, int n_in,
                              void* d_out, int out_size)
{
    const float* q     = (const float*)d_in[0];
    const float* eps   = (const float*)d_in[1];
    const float* mu_w1 = (const float*)d_in[2];
    const float* mu_b1 = (const float*)d_in[3];
    const float* mu_w2 = (const float*)d_in[4];
    const float* mu_b2 = (const float*)d_in[5];
    const float* mu_w3 = (const float*)d_in[6];
    const float* mu_b3 = (const float*)d_in[7];
    const float* lv_w1 = (const float*)d_in[8];
    const float* lv_b1 = (const float*)d_in[9];
    const float* lv_w2 = (const float*)d_in[10];
    const float* lv_b2 = (const float*)d_in[11];
    const float* lv_w3 = (const float*)d_in[12];
    const float* lv_b3 = (const float*)d_in[13];

    float* p  = (float*)d_out;                       // [B, B, D]
    float* lp = (float*)d_out + (size_t)B * B * D;   // [B, B]

    gemm1_kernel<<<dim3(8, 24), 256>>>(q, mu_w1, mu_b1, lv_w1, lv_b1);
    gemm2_kernel<<<B / 8, 256>>>(mu_w2, mu_b2, lv_w2, lv_b2);
    gemm3_kernel<<<dim3(16, 24), 256>>>(mu_w3, mu_b3, lv_w3, lv_b3);
    main_kernel<<<B * (B / IG), 256>>>(eps, p, lp);
}